// round 7
// baseline (speedup 1.0000x reference)
#include <cuda_runtime.h>
#include <cstdint>
#include <cstddef>

#define BATCH 4
#define SEQ   1024
#define EMB   1024
#define NH    16
#define HD    64
#define BH    (BATCH * NH)      // 64
#define MROWS (BATCH * SEQ)     // 4096

// ---- scratch (device globals: allocation-free per harness rules) ----
__device__ float g_q[(size_t)BH * SEQ * HD];          // [B,H,S,D] 16 MB (tf32-rounded)
__device__ float g_k[(size_t)BH * SEQ * HD];          // 16 MB (tf32-rounded)
__device__ float g_v[(size_t)BH * SEQ * HD];          // 16 MB (tf32-rounded)
__device__ float g_o[(size_t)MROWS * EMB];            // 16 MB (tf32-rounded)
__device__ float g_x[(size_t)MROWS * EMB];            // 16 MB rounded copy of x
__device__ float g_wq[(size_t)EMB * EMB];             // 4 MB rounded Wq
__device__ float g_wk[(size_t)EMB * EMB];
__device__ float g_wv[(size_t)EMB * EMB];
__device__ float g_wo[(size_t)EMB * EMB];

// tf32 round-to-nearest; result is an fp32 bit pattern whose low mantissa
// bits are zero, so feeding it raw to mma.tf32 (which truncates) is lossless.
__device__ __forceinline__ uint32_t f2tf(float f) {
    uint32_t u;
    asm("cvt.rna.tf32.f32 %0, %1;" : "=r"(u) : "f"(f));
    return u;
}
__device__ __forceinline__ float f2tff(float f) { return __uint_as_float(f2tf(f)); }

__device__ __forceinline__ void mma8(float* c, const uint32_t* a, const uint32_t* b) {
    asm volatile(
        "mma.sync.aligned.m16n8k8.row.col.f32.tf32.tf32.f32 "
        "{%0,%1,%2,%3}, {%4,%5,%6,%7}, {%8,%9}, {%0,%1,%2,%3};\n"
        : "+f"(c[0]), "+f"(c[1]), "+f"(c[2]), "+f"(c[3])
        : "r"(a[0]), "r"(a[1]), "r"(a[2]), "r"(a[3]),
          "r"(b[0]), "r"(b[1]));
}

__device__ __forceinline__ void cp16(uint32_t dst, const void* src) {
    asm volatile("cp.async.cg.shared.global [%0], [%1], 16;\n"
                 :: "r"(dst), "l"(src));
}

// ---- kernel 0: round inputs to tf32-exact fp32 in scratch ----
__global__ void __launch_bounds__(256) preround_kernel(
    const float* __restrict__ x,
    const float* __restrict__ Wq, const float* __restrict__ Wk,
    const float* __restrict__ Wv, const float* __restrict__ Wo)
{
    const int z = blockIdx.z;
    const float* src;
    float* dst;
    size_t n;
    if (z == 0)      { src = x;  dst = g_x;  n = (size_t)MROWS * EMB; }
    else if (z == 1) { src = Wq; dst = g_wq; n = (size_t)EMB * EMB; }
    else if (z == 2) { src = Wk; dst = g_wk; n = (size_t)EMB * EMB; }
    else if (z == 3) { src = Wv; dst = g_wv; n = (size_t)EMB * EMB; }
    else             { src = Wo; dst = g_wo; n = (size_t)EMB * EMB; }

    const size_t stride = (size_t)gridDim.x * blockDim.x * 4;
    for (size_t i = ((size_t)blockIdx.x * blockDim.x + threadIdx.x) * 4;
         i < n; i += stride) {
        float4 v = *reinterpret_cast<const float4*>(src + i);
        v.x = f2tff(v.x); v.y = f2tff(v.y);
        v.z = f2tff(v.z); v.w = f2tff(v.w);
        *reinterpret_cast<float4*>(dst + i) = v;
    }
}

// ============================================================================
// double-buffered cp.async tf32 GEMM core: C[M,N] = A[M,K] * B[N,K]^T
// 64x64 warp tiles: 32 mma vs 32 LDS per 8-k-step (was 16:24).
// Operands must be tf32-rounded in gmem; fragments feed raw bits to mma.
// ============================================================================
#define GC_BM 128
#define GC_BN 256
#define GC_BK 16
#define GC_WM 64
#define GC_WN 64
#define GC_LDT (GC_BK + 4)                       // 20 words
#define GC_ATILE (GC_BM * GC_LDT)                // 2560 words
#define GC_BTILE (GC_BN * GC_LDT)                // 5120 words
#define GC_SMEM_BYTES (2 * (GC_ATILE + GC_BTILE) * 4)   // 61440 B
#define GC_MT (GC_WM / 16)                       // 4
#define GC_NT (GC_WN / 8)                        // 8

__device__ __forceinline__ void gemm_core2(
    const float* __restrict__ A, int lda,
    const float* __restrict__ B, int ldb,
    int Kdim, int m0, int n0,
    float (&acc)[GC_MT][GC_NT][4])
{
    extern __shared__ float smem[];
    float* As = smem;                        // [2][BM][LDT]
    float* Bs = smem + 2 * GC_ATILE;         // [2][BN][LDT]
    const uint32_t a_sb = (uint32_t)__cvta_generic_to_shared(As);
    const uint32_t b_sb = (uint32_t)__cvta_generic_to_shared(Bs);

    const int tid  = threadIdx.x;
    const int lane = tid & 31;
    const int warp = tid >> 5;
    const int g  = lane >> 2;
    const int tg = lane & 3;
    const int wm = (warp >> 2) * GC_WM;      // warps 2 x 4
    const int wn = (warp & 3) * GC_WN;

    auto stage = [&](int buf, int k0) {
        #pragma unroll
        for (int i = 0; i < 2; ++i) {        // A: 128*16/4/256 = 2
            int idx = tid + i * 256;
            int row = idx >> 2;
            int q   = (idx & 3) << 2;
            cp16(a_sb + (uint32_t)((buf * GC_BM + row) * GC_LDT + q) * 4,
                 A + (size_t)(m0 + row) * lda + k0 + q);
        }
        #pragma unroll
        for (int i = 0; i < 4; ++i) {        // B: 256*16/4/256 = 4
            int idx = tid + i * 256;
            int row = idx >> 2;
            int q   = (idx & 3) << 2;
            cp16(b_sb + (uint32_t)((buf * GC_BN + row) * GC_LDT + q) * 4,
                 B + (size_t)(n0 + row) * ldb + k0 + q);
        }
    };

    stage(0, 0);
    asm volatile("cp.async.commit_group;\n");

    int s = 0;
    for (int k0 = 0; k0 < Kdim; k0 += GC_BK, s ^= 1) {
        if (k0 + GC_BK < Kdim) stage(s ^ 1, k0 + GC_BK);
        asm volatile("cp.async.commit_group;\n");
        asm volatile("cp.async.wait_group 1;\n");
        __syncthreads();

        const float* Ab = As + s * GC_ATILE;
        const float* Bb = Bs + s * GC_BTILE;
        #pragma unroll
        for (int ks = 0; ks < GC_BK / 8; ++ks) {
            uint32_t af[GC_MT][4];
            uint32_t bf[GC_NT][2];
            int kk0 = ks * 8 + tg, kk1 = kk0 + 4;
            #pragma unroll
            for (int mt = 0; mt < GC_MT; ++mt) {
                int r = wm + mt * 16 + g;
                af[mt][0] = __float_as_uint(Ab[r * GC_LDT + kk0]);
                af[mt][1] = __float_as_uint(Ab[(r + 8) * GC_LDT + kk0]);
                af[mt][2] = __float_as_uint(Ab[r * GC_LDT + kk1]);
                af[mt][3] = __float_as_uint(Ab[(r + 8) * GC_LDT + kk1]);
            }
            #pragma unroll
            for (int nt = 0; nt < GC_NT; ++nt) {
                int c = wn + nt * 8 + g;
                bf[nt][0] = __float_as_uint(Bb[c * GC_LDT + kk0]);
                bf[nt][1] = __float_as_uint(Bb[c * GC_LDT + kk1]);
            }
            #pragma unroll
            for (int mt = 0; mt < GC_MT; ++mt)
                #pragma unroll
                for (int nt = 0; nt < GC_NT; ++nt)
                    mma8(acc[mt][nt], af[mt], bf[nt]);
        }
        __syncthreads();
    }
}

// store rounded value into [B,H,S,D] with bias over flattened (h,d)
__device__ __forceinline__ void st_bhsd(float* __restrict__ out,
                                        const float* __restrict__ bias,
                                        int r, int c, float v) {
    int b = r >> 10, s = r & 1023;
    int h = c >> 6,  d = c & 63;
    out[(((size_t)b * NH + h) * SEQ + s) * HD + d] = f2tff(v + bias[c]);
}

// ---- kernel 1: fused QKV projection (grid.z selects q/k/v) ----
__global__ void __launch_bounds__(256, 1) qkv_kernel(
    const float* __restrict__ bq, const float* __restrict__ bk,
    const float* __restrict__ bv)
{
    const int z = blockIdx.z;
    const float* W    = (z == 0) ? g_wq : ((z == 1) ? g_wk : g_wv);
    const float* bptr = (z == 0) ? bq   : ((z == 1) ? bk   : bv);
    float* out        = (z == 0) ? g_q  : ((z == 1) ? g_k  : g_v);

    float acc[GC_MT][GC_NT][4] = {};
    const int m0 = blockIdx.x * GC_BM, n0 = blockIdx.y * GC_BN;
    gemm_core2(g_x, EMB, W, EMB, EMB, m0, n0, acc);

    const int lane = threadIdx.x & 31, warp = threadIdx.x >> 5;
    const int g = lane >> 2, tg = lane & 3;
    const int wm = (warp >> 2) * GC_WM;
    const int wn = (warp & 3) * GC_WN;
    #pragma unroll
    for (int mt = 0; mt < GC_MT; ++mt)
        #pragma unroll
        for (int nt = 0; nt < GC_NT; ++nt) {
            int r = m0 + wm + mt * 16 + g;
            int c = n0 + wn + nt * 8 + 2 * tg;
            st_bhsd(out, bptr, r,     c,     acc[mt][nt][0]);
            st_bhsd(out, bptr, r,     c + 1, acc[mt][nt][1]);
            st_bhsd(out, bptr, r + 8, c,     acc[mt][nt][2]);
            st_bhsd(out, bptr, r + 8, c + 1, acc[mt][nt][3]);
        }
}

// ---- kernel 3: out = concat @ Wo^T + bo ----
__global__ void __launch_bounds__(256, 1) oproj_kernel(
    const float* __restrict__ bo, float* __restrict__ out)
{
    float acc[GC_MT][GC_NT][4] = {};
    const int m0 = blockIdx.x * GC_BM, n0 = blockIdx.y * GC_BN;
    gemm_core2(g_o, EMB, g_wo, EMB, EMB, m0, n0, acc);

    const int lane = threadIdx.x & 31, warp = threadIdx.x >> 5;
    const int g = lane >> 2, tg = lane & 3;
    const int wm = (warp >> 2) * GC_WM;
    const int wn = (warp & 3) * GC_WN;
    #pragma unroll
    for (int mt = 0; mt < GC_MT; ++mt)
        #pragma unroll
        for (int nt = 0; nt < GC_NT; ++nt) {
            int r = m0 + wm + mt * 16 + g;
            int c = n0 + wn + nt * 8 + 2 * tg;
            out[(size_t)r * EMB + c]           = acc[mt][nt][0] + bo[c];
            out[(size_t)r * EMB + c + 1]       = acc[mt][nt][1] + bo[c + 1];
            out[(size_t)(r + 8) * EMB + c]     = acc[mt][nt][2] + bo[c];
            out[(size_t)(r + 8) * EMB + c + 1] = acc[mt][nt][3] + bo[c + 1];
        }
}

// ============================================================================
// kernel 2: fused flash attention — raw-bit tf32 on pre-rounded q/k/v,
// cp.async staging, natural layouts, conflict-free fragment strides.
// Qs [128][68], Ks [64][68], Vs [64][72], Ps [128][76]   (unchanged R6)
// ============================================================================
#define FA_BM 128
#define FA_BN 64
#define FA_QLD 68
#define FA_KLD 68
#define FA_VLD 72
#define FA_PLD 76
#define FA_QS_SZ (128 * FA_QLD)
#define FA_KS_SZ (64 * FA_KLD)
#define FA_VS_SZ (64 * FA_VLD)
#define FA_PS_SZ (128 * FA_PLD)
#define FA_SMEM_WORDS (FA_QS_SZ + FA_KS_SZ + FA_VS_SZ + FA_PS_SZ + 512)

__global__ void __launch_bounds__(256, 2) flash_kernel()
{
    extern __shared__ float fsm[];
    float* Qs = fsm;
    float* Ks = Qs + FA_QS_SZ;
    float* Vs = Ks + FA_KS_SZ;
    float* Ps = Vs + FA_VS_SZ;
    float* redA = Ps + FA_PS_SZ;    // [2][128]
    float* redB = redA + 256;       // [2][128]
    const uint32_t qs_b = (uint32_t)__cvta_generic_to_shared(Qs);
    const uint32_t ks_b = (uint32_t)__cvta_generic_to_shared(Ks);
    const uint32_t vs_b = (uint32_t)__cvta_generic_to_shared(Vs);

    const int z  = blockIdx.z;
    const int m0 = blockIdx.x * FA_BM;
    const float* Q  = g_q + (size_t)z * SEQ * HD;
    const float* Kg = g_k + (size_t)z * SEQ * HD;
    const float* Vg = g_v + (size_t)z * SEQ * HD;

    const int tid  = threadIdx.x;
    const int lane = tid & 31, warp = tid >> 5;
    const int g = lane >> 2, tg = lane & 3;
    const int mw = warp >> 1, nw = warp & 1;
    const int wm = mw * 32;
    const int wn = nw * 32;

    #pragma unroll
    for (int i = 0; i < 8; ++i) {
        int idx = tid + i * 256;
        int r  = idx >> 4;
        int dq = (idx & 15) << 2;
        cp16(qs_b + (uint32_t)(r * FA_QLD + dq) * 4,
             Q + (size_t)(m0 + r) * HD + dq);
    }
    asm volatile("cp.async.commit_group;\n");

    float acc_o[2][4][4] = {};
    float m_st[2][2] = {{-1e30f, -1e30f}, {-1e30f, -1e30f}};
    float l_st[2][2] = {};

    for (int n0 = 0; n0 < SEQ; n0 += FA_BN) {
        __syncthreads();

        #pragma unroll
        for (int i = 0; i < 4; ++i) {
            int idx = tid + i * 256;
            int n  = idx >> 4;
            int dq = (idx & 15) << 2;
            cp16(ks_b + (uint32_t)(n * FA_KLD + dq) * 4,
                 Kg + (size_t)(n0 + n) * HD + dq);
            cp16(vs_b + (uint32_t)(n * FA_VLD + dq) * 4,
                 Vg + (size_t)(n0 + n) * HD + dq);
        }
        asm volatile("cp.async.commit_group;\n");
        asm volatile("cp.async.wait_group 0;\n");
        __syncthreads();

        // ---- S = Q K^T ----
        float acc_s[2][4][4] = {};
        #pragma unroll
        for (int ks = 0; ks < 8; ++ks) {
            uint32_t af[2][4];
            uint32_t bf[4][2];
            int kk0 = ks * 8 + tg, kk1 = kk0 + 4;
            #pragma unroll
            for (int mt = 0; mt < 2; ++mt) {
                int r = wm + mt * 16 + g;
                af[mt][0] = __float_as_uint(Qs[r * FA_QLD + kk0]);
                af[mt][1] = __float_as_uint(Qs[(r + 8) * FA_QLD + kk0]);
                af[mt][2] = __float_as_uint(Qs[r * FA_QLD + kk1]);
                af[mt][3] = __float_as_uint(Qs[(r + 8) * FA_QLD + kk1]);
            }
            #pragma unroll
            for (int nt = 0; nt < 4; ++nt) {
                int c = wn + nt * 8 + g;
                bf[nt][0] = __float_as_uint(Ks[c * FA_KLD + kk0]);
                bf[nt][1] = __float_as_uint(Ks[c * FA_KLD + kk1]);
            }
            #pragma unroll
            for (int mt = 0; mt < 2; ++mt)
                #pragma unroll
                for (int nt = 0; nt < 4; ++nt)
                    mma8(acc_s[mt][nt], af[mt], bf[nt]);
        }
        #pragma unroll
        for (int mt = 0; mt < 2; ++mt)
            #pragma unroll
            for (int nt = 0; nt < 4; ++nt)
                #pragma unroll
                for (int e = 0; e < 4; ++e)
                    acc_s[mt][nt][e] *= 0.125f;

        // ---- row max ----
        #pragma unroll
        for (int mt = 0; mt < 2; ++mt)
            #pragma unroll
            for (int h = 0; h < 2; ++h) {
                float m = -1e30f;
                #pragma unroll
                for (int nt = 0; nt < 4; ++nt)
                    m = fmaxf(m, fmaxf(acc_s[mt][nt][2 * h], acc_s[mt][nt][2 * h + 1]));
                m = fmaxf(m, __shfl_xor_sync(0xffffffffu, m, 1));
                m = fmaxf(m, __shfl_xor_sync(0xffffffffu, m, 2));
                if (tg == 0) redA[nw * 128 + wm + mt * 16 + g + 8 * h] = m;
            }
        __syncthreads();

        // ---- online softmax + write rounded P ----
        #pragma unroll
        for (int mt = 0; mt < 2; ++mt)
            #pragma unroll
            for (int h = 0; h < 2; ++h) {
                int row = wm + mt * 16 + g + 8 * h;
                float m = fmaxf(redA[row], redA[128 + row]);
                float mnew = fmaxf(m_st[mt][h], m);
                float scale = __expf(m_st[mt][h] - mnew);
                m_st[mt][h] = mnew;
                l_st[mt][h] *= scale;
                #pragma unroll
                for (int nt = 0; nt < 4; ++nt) {
                    acc_o[mt][nt][2 * h]     *= scale;
                    acc_o[mt][nt][2 * h + 1] *= scale;
                }
                float rs = 0.f;
                #pragma unroll
                for (int nt = 0; nt < 4; ++nt) {
                    int c = wn + nt * 8 + 2 * tg;
                    float p0 = __expf(acc_s[mt][nt][2 * h]     - mnew);
                    float p1 = __expf(acc_s[mt][nt][2 * h + 1] - mnew);
                    rs += p0 + p1;
                    Ps[row * FA_PLD + c]     = f2tff(p0);
                    Ps[row * FA_PLD + c + 1] = f2tff(p1);
                }
                rs += __shfl_xor_sync(0xffffffffu, rs, 1);
                rs += __shfl_xor_sync(0xffffffffu, rs, 2);
                if (tg == 0) redB[nw * 128 + row] = rs;
            }
        __syncthreads();

        #pragma unroll
        for (int mt = 0; mt < 2; ++mt)
            #pragma unroll
            for (int h = 0; h < 2; ++h) {
                int row = wm + mt * 16 + g + 8 * h;
                l_st[mt][h] += redB[row] + redB[128 + row];
            }

        // ---- O += P V ----
        #pragma unroll
        for (int ks = 0; ks < 8; ++ks) {
            uint32_t af[2][4];
            uint32_t bf[4][2];
            int kk0 = ks * 8 + tg, kk1 = kk0 + 4;
            #pragma unroll
            for (int mt = 0; mt < 2; ++mt) {
                int r = wm + mt * 16 + g;
                af[mt][0] = __float_as_uint(Ps[r * FA_PLD + kk0]);
                af[mt][1] = __float_as_uint(Ps[(r + 8) * FA_PLD + kk0]);
                af[mt][2] = __float_as_uint(Ps[r * FA_PLD + kk1]);
                af[mt][3] = __float_as_uint(Ps[(r + 8) * FA_PLD + kk1]);
            }
            #pragma unroll
            for (int nt = 0; nt < 4; ++nt) {
                int d = wn + nt * 8 + g;
                bf[nt][0] = __float_as_uint(Vs[kk0 * FA_VLD + d]);
                bf[nt][1] = __float_as_uint(Vs[kk1 * FA_VLD + d]);
            }
            #pragma unroll
            for (int mt = 0; mt < 2; ++mt)
                #pragma unroll
                for (int nt = 0; nt < 4; ++nt)
                    mma8(acc_o[mt][nt], af[mt], bf[nt]);
        }
    }

    // ---- epilogue: O /= l, rounded for oproj, concat layout [B,S,H*D] ----
    const int b = z >> 4, h = z & 15;
    #pragma unroll
    for (int mt = 0; mt < 2; ++mt) {
        float inv0 = 1.0f / l_st[mt][0];
        float inv1 = 1.0f / l_st[mt][1];
        #pragma unroll
        for (int nt = 0; nt < 4; ++nt) {
            int s0 = m0 + wm + mt * 16 + g;
            int d0 = wn + nt * 8 + 2 * tg;
            size_t base0 = ((size_t)(b * SEQ + s0)) * EMB + h * HD;
            size_t base1 = base0 + (size_t)8 * EMB;
            g_o[base0 + d0]     = f2tff(acc_o[mt][nt][0] * inv0);
            g_o[base0 + d0 + 1] = f2tff(acc_o[mt][nt][1] * inv0);
            g_o[base1 + d0]     = f2tff(acc_o[mt][nt][2] * inv1);
            g_o[base1 + d0 + 1] = f2tff(acc_o[mt][nt][3] * inv1);
        }
    }
}

extern "C" void kernel_launch(void* const* d_in, const int* in_sizes, int n_in,
                              void* d_out, int out_size)
{
    const float* x  = (const float*)d_in[0];
    const float* Wq = (const float*)d_in[1];
    const float* bq = (const float*)d_in[2];
    const float* Wk = (const float*)d_in[3];
    const float* bk = (const float*)d_in[4];
    const float* Wv = (const float*)d_in[5];
    const float* bv = (const float*)d_in[6];
    const float* Wo = (const float*)d_in[7];
    const float* bo = (const float*)d_in[8];
    float* out = (float*)d_out;

    const int gc_smem = GC_SMEM_BYTES;       // 61440 B
    const int fa_smem = FA_SMEM_WORDS * 4;   // 111616 B
    cudaFuncSetAttribute(qkv_kernel,
                         cudaFuncAttributeMaxDynamicSharedMemorySize, gc_smem);
    cudaFuncSetAttribute(oproj_kernel,
                         cudaFuncAttributeMaxDynamicSharedMemorySize, gc_smem);
    cudaFuncSetAttribute(flash_kernel,
                         cudaFuncAttributeMaxDynamicSharedMemorySize, fa_smem);

    preround_kernel<<<dim3(1024, 1, 5), 256>>>(x, Wq, Wk, Wv, Wo);
    qkv_kernel<<<dim3(MROWS / GC_BM, EMB / GC_BN, 3), 256, gc_smem>>>(bq, bk, bv);
    flash_kernel<<<dim3(SEQ / FA_BM, 1, BH), 256, fa_smem>>>();
    oproj_kernel<<<dim3(MROWS / GC_BM, EMB / GC_BN, 1), 256, gc_smem>>>(bo, out);
}

// round 9
// speedup vs baseline: 1.9067x; 1.9067x over previous
#include <cuda_runtime.h>
#include <cuda_fp16.h>
#include <cstdint>
#include <cstddef>

#define BATCH 4
#define SEQ   1024
#define EMB   1024
#define NH    16
#define HD    64
#define BH    (BATCH * NH)      // 64
#define MROWS (BATCH * SEQ)     // 4096

// ---- scratch (device globals: allocation-free per harness rules) ----
__device__ __half g_xh[(size_t)MROWS * EMB];          // rounded x (8 MB)
__device__ __half g_wqh[(size_t)EMB * EMB];           // 2 MB each
__device__ __half g_wkh[(size_t)EMB * EMB];
__device__ __half g_wvh[(size_t)EMB * EMB];
__device__ __half g_woh[(size_t)EMB * EMB];
__device__ __half g_qh[(size_t)BH * SEQ * HD];        // [B,H,S,D]
__device__ __half g_kh[(size_t)BH * SEQ * HD];        // [B,H,S,D]
__device__ __half g_vh[(size_t)BH * SEQ * HD];        // [B,H,D,S]  (TRANSPOSED)
__device__ __half g_oh[(size_t)MROWS * EMB];          // [B,S,H*D] concat

// fp16 mma m16n8k16, fp32 accumulate
__device__ __forceinline__ void mma16(float* c, const uint32_t* a, const uint32_t* b) {
    asm volatile(
        "mma.sync.aligned.m16n8k16.row.col.f32.f16.f16.f32 "
        "{%0,%1,%2,%3}, {%4,%5,%6,%7}, {%8,%9}, {%0,%1,%2,%3};\n"
        : "+f"(c[0]), "+f"(c[1]), "+f"(c[2]), "+f"(c[3])
        : "r"(a[0]), "r"(a[1]), "r"(a[2]), "r"(a[3]),
          "r"(b[0]), "r"(b[1]));
}

__device__ __forceinline__ void cp16(uint32_t dst, const void* src) {
    asm volatile("cp.async.cg.shared.global [%0], [%1], 16;\n"
                 :: "r"(dst), "l"(src));
}

__device__ __forceinline__ uint32_t smem_u32(const void* p) {
    uint32_t a;
    asm("{ .reg .u64 t; cvta.to.shared.u64 t, %1; cvt.u32.u64 %0, t; }"
        : "=r"(a) : "l"(p));
    return a;
}

__device__ __forceinline__ uint32_t h2_bits(__half2 h) {
    return *reinterpret_cast<uint32_t*>(&h);
}

// ---- kernel 0: convert inputs to fp16 in scratch ----
__global__ void __launch_bounds__(256) convert_kernel(
    const float* __restrict__ x,
    const float* __restrict__ Wq, const float* __restrict__ Wk,
    const float* __restrict__ Wv, const float* __restrict__ Wo)
{
    const int z = blockIdx.z;
    const float* src;
    __half* dst;
    size_t n;
    if (z == 0)      { src = x;  dst = g_xh;  n = (size_t)MROWS * EMB; }
    else if (z == 1) { src = Wq; dst = g_wqh; n = (size_t)EMB * EMB; }
    else if (z == 2) { src = Wk; dst = g_wkh; n = (size_t)EMB * EMB; }
    else if (z == 3) { src = Wv; dst = g_wvh; n = (size_t)EMB * EMB; }
    else             { src = Wo; dst = g_woh; n = (size_t)EMB * EMB; }

    const size_t stride = (size_t)gridDim.x * blockDim.x * 4;
    for (size_t i = ((size_t)blockIdx.x * blockDim.x + threadIdx.x) * 4;
         i < n; i += stride) {
        float4 v = *reinterpret_cast<const float4*>(src + i);
        __half2* d2 = reinterpret_cast<__half2*>(dst + i);
        d2[0] = __floats2half2_rn(v.x, v.y);
        d2[1] = __floats2half2_rn(v.z, v.w);
    }
}

// ============================================================================
// double-buffered cp.async fp16 GEMM core: C[M,N] = A[M,K] * B[N,K]^T
// BM=128, BN=128, BK=64 halves; warp tile 64x32; 8 warps (2x4).
// smem rows stored as 32 uints (64 halves) + pad 4 -> stride 36 uints.
// ============================================================================
#define GH_BM 128
#define GH_BN 128
#define GH_BK 64                      // halves per k-chunk
#define GH_LDT 36                     // uints per row (32 + 4 pad)
#define GH_TILE (128 * GH_LDT)        // 4608 uints per operand per buffer
#define GH_SMEM_BYTES (2 * 2 * GH_TILE * 4)   // 73728 B
#define GH_MT 4
#define GH_NT 4

__device__ __forceinline__ void gemm_core_h(
    const __half* __restrict__ A,
    const __half* __restrict__ B,
    int Kdim, int m0, int n0,
    float (&acc)[GH_MT][GH_NT][4])
{
    extern __shared__ uint32_t smh[];
    uint32_t* As = smh;                      // [2][128][36]
    uint32_t* Bs = smh + 2 * GH_TILE;        // [2][128][36]
    const uint32_t a_sb = smem_u32(As);
    const uint32_t b_sb = smem_u32(Bs);

    const int tid  = threadIdx.x;
    const int lane = tid & 31;
    const int warp = tid >> 5;
    const int g  = lane >> 2;
    const int tg = lane & 3;
    const int wm = (warp >> 2) * 64;         // 2 warp-rows
    const int wn = (warp & 3) * 32;          // 4 warp-cols

    auto stage = [&](int buf, int k0) {
        #pragma unroll
        for (int i = 0; i < 4; ++i) {        // A: 128 rows x 8 cp16
            int idx = tid + i * 256;
            int row = idx >> 3, q = idx & 7;
            cp16(a_sb + (uint32_t)((buf * GH_BM + row) * GH_LDT + q * 4) * 4,
                 A + (size_t)(m0 + row) * Kdim + k0 + q * 8);
        }
        #pragma unroll
        for (int i = 0; i < 4; ++i) {        // B: 128 rows x 8 cp16
            int idx = tid + i * 256;
            int row = idx >> 3, q = idx & 7;
            cp16(b_sb + (uint32_t)((buf * GH_BN + row) * GH_LDT + q * 4) * 4,
                 B + (size_t)(n0 + row) * Kdim + k0 + q * 8);
        }
    };

    stage(0, 0);
    asm volatile("cp.async.commit_group;\n");

    int s = 0;
    for (int k0 = 0; k0 < Kdim; k0 += GH_BK, s ^= 1) {
        if (k0 + GH_BK < Kdim) stage(s ^ 1, k0 + GH_BK);
        asm volatile("cp.async.commit_group;\n");
        asm volatile("cp.async.wait_group 1;\n");
        __syncthreads();

        const uint32_t* Ab = As + s * GH_TILE;
        const uint32_t* Bb = Bs + s * GH_TILE;
        #pragma unroll
        for (int ks = 0; ks < 4; ++ks) {     // 4 k16 steps per chunk
            uint32_t af[GH_MT][4];
            uint32_t bf[GH_NT][2];
            int ku0 = ks * 8 + tg, ku1 = ku0 + 4;
            #pragma unroll
            for (int mt = 0; mt < GH_MT; ++mt) {
                int r = wm + mt * 16 + g;
                af[mt][0] = Ab[r * GH_LDT + ku0];
                af[mt][1] = Ab[(r + 8) * GH_LDT + ku0];
                af[mt][2] = Ab[r * GH_LDT + ku1];
                af[mt][3] = Ab[(r + 8) * GH_LDT + ku1];
            }
            #pragma unroll
            for (int nt = 0; nt < GH_NT; ++nt) {
                int c = wn + nt * 8 + g;
                bf[nt][0] = Bb[c * GH_LDT + ku0];
                bf[nt][1] = Bb[c * GH_LDT + ku1];
            }
            #pragma unroll
            for (int mt = 0; mt < GH_MT; ++mt)
                #pragma unroll
                for (int nt = 0; nt < GH_NT; ++nt)
                    mma16(acc[mt][nt], af[mt], bf[nt]);
        }
        __syncthreads();
    }
}

// ---- kernel 1: fused QKV projection (grid.z selects q/k/v) ----
// q,k stored [B,H,S,D]; v stored TRANSPOSED [B,H,D,S] for flash PV mma.
__global__ void __launch_bounds__(256, 2) qkv_kernel(
    const float* __restrict__ bq, const float* __restrict__ bk,
    const float* __restrict__ bv)
{
    const int z = blockIdx.z;
    const __half* W   = (z == 0) ? g_wqh : ((z == 1) ? g_wkh : g_wvh);
    const float* bptr = (z == 0) ? bq    : ((z == 1) ? bk    : bv);
    __half* out       = (z == 0) ? g_qh  : ((z == 1) ? g_kh  : g_vh);

    float acc[GH_MT][GH_NT][4] = {};
    const int m0 = blockIdx.x * GH_BM, n0 = blockIdx.y * GH_BN;
    gemm_core_h(g_xh, W, EMB, m0, n0, acc);

    const int lane = threadIdx.x & 31, warp = threadIdx.x >> 5;
    const int g = lane >> 2, tg = lane & 3;
    const int wm = (warp >> 2) * 64;
    const int wn = (warp & 3) * 32;

    #pragma unroll
    for (int mt = 0; mt < GH_MT; ++mt)
        #pragma unroll
        for (int nt = 0; nt < GH_NT; ++nt) {
            int r = m0 + wm + mt * 16 + g;
            int c = n0 + wn + nt * 8 + 2 * tg;       // even
            float v0 = acc[mt][nt][0] + bptr[c];
            float v1 = acc[mt][nt][1] + bptr[c + 1];
            float v2 = acc[mt][nt][2] + bptr[c];
            float v3 = acc[mt][nt][3] + bptr[c + 1];
            int h = c >> 6, d = c & 63;
            int b0 = r >> 10, s0 = r & 1023;
            int b1 = (r + 8) >> 10, s1 = (r + 8) & 1023;
            if (z < 2) {
                // [B,H,S,D]; d even -> half2 pair
                __half2* p0 = reinterpret_cast<__half2*>(
                    out + (((size_t)b0 * NH + h) * SEQ + s0) * HD + d);
                __half2* p1 = reinterpret_cast<__half2*>(
                    out + (((size_t)b1 * NH + h) * SEQ + s1) * HD + d);
                *p0 = __floats2half2_rn(v0, v1);
                *p1 = __floats2half2_rn(v2, v3);
            } else {
                // transposed [B,H,D,S]
                out[(((size_t)b0 * NH + h) * HD + d) * SEQ + s0]     = __float2half_rn(v0);
                out[(((size_t)b0 * NH + h) * HD + d + 1) * SEQ + s0] = __float2half_rn(v1);
                out[(((size_t)b1 * NH + h) * HD + d) * SEQ + s1]     = __float2half_rn(v2);
                out[(((size_t)b1 * NH + h) * HD + d + 1) * SEQ + s1] = __float2half_rn(v3);
            }
        }
}

// ---- kernel 3: out = concat @ Wo^T + bo (fp32 output) ----
__global__ void __launch_bounds__(256, 2) oproj_kernel(
    const float* __restrict__ bo, float* __restrict__ out)
{
    float acc[GH_MT][GH_NT][4] = {};
    const int m0 = blockIdx.x * GH_BM, n0 = blockIdx.y * GH_BN;
    gemm_core_h(g_oh, g_woh, EMB, m0, n0, acc);

    const int lane = threadIdx.x & 31, warp = threadIdx.x >> 5;
    const int g = lane >> 2, tg = lane & 3;
    const int wm = (warp >> 2) * 64;
    const int wn = (warp & 3) * 32;
    #pragma unroll
    for (int mt = 0; mt < GH_MT; ++mt)
        #pragma unroll
        for (int nt = 0; nt < GH_NT; ++nt) {
            int r = m0 + wm + mt * 16 + g;
            int c = n0 + wn + nt * 8 + 2 * tg;
            out[(size_t)r * EMB + c]           = acc[mt][nt][0] + bo[c];
            out[(size_t)r * EMB + c + 1]       = acc[mt][nt][1] + bo[c + 1];
            out[(size_t)(r + 8) * EMB + c]     = acc[mt][nt][2] + bo[c];
            out[(size_t)(r + 8) * EMB + c + 1] = acc[mt][nt][3] + bo[c + 1];
        }
}

// ============================================================================
// kernel 2: fused flash attention, fp16 mma (k16), fp32 softmax.
// Qu[128][36], Ku[64][36], Vu[64][36] (V is d-major!), Pu[128][36] (uints)
// ============================================================================
#define FA_BM 128
#define FA_BN 64
#define FA_LDT 36
#define FA_QS (128 * FA_LDT)
#define FA_KS (64 * FA_LDT)
#define FA_VS (64 * FA_LDT)
#define FA_PS (128 * FA_LDT)
#define FA_SMEM_BYTES ((FA_QS + FA_KS + FA_VS + FA_PS + 512) * 4)   // 59392 B

__global__ void __launch_bounds__(256, 2) flash_kernel()
{
    extern __shared__ uint32_t fsh[];
    uint32_t* Qu = fsh;
    uint32_t* Ku = Qu + FA_QS;
    uint32_t* Vu = Ku + FA_KS;
    uint32_t* Pu = Vu + FA_VS;
    float* redA  = (float*)(Pu + FA_PS);     // [2][128]
    float* redB  = redA + 256;               // [2][128]
    const uint32_t qu_b = smem_u32(Qu);
    const uint32_t ku_b = smem_u32(Ku);
    const uint32_t vu_b = smem_u32(Vu);

    const int z  = blockIdx.z;
    const int m0 = blockIdx.x * FA_BM;
    const __half* Qh = g_qh + (size_t)z * SEQ * HD;
    const __half* Kh = g_kh + (size_t)z * SEQ * HD;
    const __half* Vh = g_vh + (size_t)z * HD * SEQ;   // [D][S]

    const int tid  = threadIdx.x;
    const int lane = tid & 31, warp = tid >> 5;
    const int g = lane >> 2, tg = lane & 3;
    const int mw = warp >> 1, nw = warp & 1;
    const int wm = mw * 32;
    const int wn = nw * 32;

    // stage Q tile once: 128 rows x 8 cp16
    #pragma unroll
    for (int i = 0; i < 4; ++i) {
        int idx = tid + i * 256;
        int r = idx >> 3, q = idx & 7;
        cp16(qu_b + (uint32_t)(r * FA_LDT + q * 4) * 4,
             Qh + (size_t)(m0 + r) * HD + q * 8);
    }
    asm volatile("cp.async.commit_group;\n");

    float acc_o[2][4][4] = {};
    float m_st[2][2] = {{-1e30f, -1e30f}, {-1e30f, -1e30f}};
    float l_st[2][2] = {};

    for (int n0 = 0; n0 < SEQ; n0 += FA_BN) {
        __syncthreads();   // prior iter's Ku/Vu/Pu reads complete

        // K: 64 key-rows x 8 cp16; V: 64 d-rows x 8 cp16 (keys contiguous)
        #pragma unroll
        for (int i = 0; i < 2; ++i) {
            int idx = tid + i * 256;
            int rr = idx >> 3, q = idx & 7;
            cp16(ku_b + (uint32_t)(rr * FA_LDT + q * 4) * 4,
                 Kh + (size_t)(n0 + rr) * HD + q * 8);
            cp16(vu_b + (uint32_t)(rr * FA_LDT + q * 4) * 4,
                 Vh + (size_t)rr * SEQ + n0 + q * 8);
        }
        asm volatile("cp.async.commit_group;\n");
        asm volatile("cp.async.wait_group 0;\n");
        __syncthreads();

        // ---- S = Q K^T (4 k16 steps over D=64) ----
        float acc_s[2][4][4] = {};
        #pragma unroll
        for (int ks = 0; ks < 4; ++ks) {
            uint32_t af[2][4];
            uint32_t bf[4][2];
            int ku0 = ks * 8 + tg, ku1 = ku0 + 4;
            #pragma unroll
            for (int mt = 0; mt < 2; ++mt) {
                int r = wm + mt * 16 + g;
                af[mt][0] = Qu[r * FA_LDT + ku0];
                af[mt][1] = Qu[(r + 8) * FA_LDT + ku0];
                af[mt][2] = Qu[r * FA_LDT + ku1];
                af[mt][3] = Qu[(r + 8) * FA_LDT + ku1];
            }
            #pragma unroll
            for (int nt = 0; nt < 4; ++nt) {
                int c = wn + nt * 8 + g;
                bf[nt][0] = Ku[c * FA_LDT + ku0];
                bf[nt][1] = Ku[c * FA_LDT + ku1];
            }
            #pragma unroll
            for (int mt = 0; mt < 2; ++mt)
                #pragma unroll
                for (int nt = 0; nt < 4; ++nt)
                    mma16(acc_s[mt][nt], af[mt], bf[nt]);
        }
        #pragma unroll
        for (int mt = 0; mt < 2; ++mt)
            #pragma unroll
            for (int nt = 0; nt < 4; ++nt)
                #pragma unroll
                for (int e = 0; e < 4; ++e)
                    acc_s[mt][nt][e] *= 0.125f;

        // ---- row max (quad shuffle + cross-nw smem) ----
        #pragma unroll
        for (int mt = 0; mt < 2; ++mt)
            #pragma unroll
            for (int h = 0; h < 2; ++h) {
                float m = -1e30f;
                #pragma unroll
                for (int nt = 0; nt < 4; ++nt)
                    m = fmaxf(m, fmaxf(acc_s[mt][nt][2 * h], acc_s[mt][nt][2 * h + 1]));
                m = fmaxf(m, __shfl_xor_sync(0xffffffffu, m, 1));
                m = fmaxf(m, __shfl_xor_sync(0xffffffffu, m, 2));
                if (tg == 0) redA[nw * 128 + wm + mt * 16 + g + 8 * h] = m;
            }
        __syncthreads();

        // ---- online softmax + write P (half2 packed) ----
        #pragma unroll
        for (int mt = 0; mt < 2; ++mt)
            #pragma unroll
            for (int h = 0; h < 2; ++h) {
                int row = wm + mt * 16 + g + 8 * h;
                float m = fmaxf(redA[row], redA[128 + row]);
                float mnew = fmaxf(m_st[mt][h], m);
                float scale = __expf(m_st[mt][h] - mnew);
                m_st[mt][h] = mnew;
                l_st[mt][h] *= scale;
                #pragma unroll
                for (int nt = 0; nt < 4; ++nt) {
                    acc_o[mt][nt][2 * h]     *= scale;
                    acc_o[mt][nt][2 * h + 1] *= scale;
                }
                float rs = 0.f;
                #pragma unroll
                for (int nt = 0; nt < 4; ++nt) {
                    float p0 = __expf(acc_s[mt][nt][2 * h]     - mnew);
                    float p1 = __expf(acc_s[mt][nt][2 * h + 1] - mnew);
                    rs += p0 + p1;
                    Pu[row * FA_LDT + (wn >> 1) + nt * 4 + tg] =
                        h2_bits(__floats2half2_rn(p0, p1));
                }
                rs += __shfl_xor_sync(0xffffffffu, rs, 1);
                rs += __shfl_xor_sync(0xffffffffu, rs, 2);
                if (tg == 0) redB[nw * 128 + row] = rs;
            }
        __syncthreads();   // P + redB visible across warps

        #pragma unroll
        for (int mt = 0; mt < 2; ++mt)
            #pragma unroll
            for (int h = 0; h < 2; ++h) {
                int row = wm + mt * 16 + g + 8 * h;
                l_st[mt][h] += redB[row] + redB[128 + row];
            }

        // ---- O += P V (4 k16 steps over 64 keys) ----
        #pragma unroll
        for (int ks = 0; ks < 4; ++ks) {
            uint32_t af[2][4];
            uint32_t bf[4][2];
            int ku0 = ks * 8 + tg, ku1 = ku0 + 4;
            #pragma unroll
            for (int mt = 0; mt < 2; ++mt) {
                int r = wm + mt * 16 + g;
                af[mt][0] = Pu[r * FA_LDT + ku0];
                af[mt][1] = Pu[(r + 8) * FA_LDT + ku0];
                af[mt][2] = Pu[r * FA_LDT + ku1];
                af[mt][3] = Pu[(r + 8) * FA_LDT + ku1];
            }
            #pragma unroll
            for (int nt = 0; nt < 4; ++nt) {
                int d = wn + nt * 8 + g;
                bf[nt][0] = Vu[d * FA_LDT + ku0];
                bf[nt][1] = Vu[d * FA_LDT + ku1];
            }
            #pragma unroll
            for (int mt = 0; mt < 2; ++mt)
                #pragma unroll
                for (int nt = 0; nt < 4; ++nt)
                    mma16(acc_o[mt][nt], af[mt], bf[nt]);
        }
    }

    // ---- epilogue: O /= l, half2 stores into concat layout [B,S,H*D] ----
    const int b = z >> 4, h = z & 15;
    #pragma unroll
    for (int mt = 0; mt < 2; ++mt) {
        float inv0 = 1.0f / l_st[mt][0];
        float inv1 = 1.0f / l_st[mt][1];
        #pragma unroll
        for (int nt = 0; nt < 4; ++nt) {
            int s0 = m0 + wm + mt * 16 + g;
            int d0 = wn + nt * 8 + 2 * tg;           // even
            size_t base0 = ((size_t)(b * SEQ + s0)) * EMB + h * HD + d0;
            size_t base1 = ((size_t)(b * SEQ + s0 + 8)) * EMB + h * HD + d0;
            *reinterpret_cast<__half2*>(g_oh + base0) =
                __floats2half2_rn(acc_o[mt][nt][0] * inv0, acc_o[mt][nt][1] * inv0);
            *reinterpret_cast<__half2*>(g_oh + base1) =
                __floats2half2_rn(acc_o[mt][nt][2] * inv1, acc_o[mt][nt][3] * inv1);
        }
    }
}

extern "C" void kernel_launch(void* const* d_in, const int* in_sizes, int n_in,
                              void* d_out, int out_size)
{
    const float* x  = (const float*)d_in[0];
    const float* Wq = (const float*)d_in[1];
    const float* bq = (const float*)d_in[2];
    const float* Wk = (const float*)d_in[3];
    const float* bk = (const float*)d_in[4];
    const float* Wv = (const float*)d_in[5];
    const float* bv = (const float*)d_in[6];
    const float* Wo = (const float*)d_in[7];
    const float* bo = (const float*)d_in[8];
    float* out = (float*)d_out;

    cudaFuncSetAttribute(qkv_kernel,
                         cudaFuncAttributeMaxDynamicSharedMemorySize, GH_SMEM_BYTES);
    cudaFuncSetAttribute(oproj_kernel,
                         cudaFuncAttributeMaxDynamicSharedMemorySize, GH_SMEM_BYTES);
    cudaFuncSetAttribute(flash_kernel,
                         cudaFuncAttributeMaxDynamicSharedMemorySize, FA_SMEM_BYTES);

    convert_kernel<<<dim3(1024, 1, 5), 256>>>(x, Wq, Wk, Wv, Wo);
    qkv_kernel<<<dim3(MROWS / GH_BM, EMB / GH_BN, 3), 256, GH_SMEM_BYTES>>>(bq, bk, bv);
    flash_kernel<<<dim3(SEQ / FA_BM, 1, BH), 256, FA_SMEM_BYTES>>>();
    oproj_kernel<<<dim3(MROWS / GH_BM, EMB / GH_BN, 1), 256, GH_SMEM_BYTES>>>(bo, out);
}

// round 10
// speedup vs baseline: 2.0176x; 1.0582x over previous
#include <cuda_runtime.h>
#include <cuda_fp16.h>
#include <cstdint>
#include <cstddef>

#define BATCH 4
#define SEQ   1024
#define EMB   1024
#define NH    16
#define HD    64
#define BH    (BATCH * NH)      // 64
#define MROWS (BATCH * SEQ)     // 4096

// ---- scratch (device globals: allocation-free per harness rules) ----
__device__ __half g_xh[(size_t)MROWS * EMB];          // rounded x (8 MB)
__device__ __half g_wqh[(size_t)EMB * EMB];           // 2 MB each
__device__ __half g_wkh[(size_t)EMB * EMB];
__device__ __half g_wvh[(size_t)EMB * EMB];
__device__ __half g_woh[(size_t)EMB * EMB];
__device__ __half g_qh[(size_t)BH * SEQ * HD];        // [B,H,S,D]
__device__ __half g_kh[(size_t)BH * SEQ * HD];        // [B,H,S,D]
__device__ __half g_vh[(size_t)BH * SEQ * HD];        // [B,H,D,S]  (TRANSPOSED)
__device__ __half g_oh[(size_t)MROWS * EMB];          // [B,S,H*D] concat

// fp16 mma m16n8k16, fp32 accumulate
__device__ __forceinline__ void mma16(float* c, const uint32_t* a, const uint32_t* b) {
    asm volatile(
        "mma.sync.aligned.m16n8k16.row.col.f32.f16.f16.f32 "
        "{%0,%1,%2,%3}, {%4,%5,%6,%7}, {%8,%9}, {%0,%1,%2,%3};\n"
        : "+f"(c[0]), "+f"(c[1]), "+f"(c[2]), "+f"(c[3])
        : "r"(a[0]), "r"(a[1]), "r"(a[2]), "r"(a[3]),
          "r"(b[0]), "r"(b[1]));
}

__device__ __forceinline__ void cp16(uint32_t dst, const void* src) {
    asm volatile("cp.async.cg.shared.global [%0], [%1], 16;\n"
                 :: "r"(dst), "l"(src));
}

__device__ __forceinline__ void ldsm4(uint32_t& r0, uint32_t& r1,
                                      uint32_t& r2, uint32_t& r3, uint32_t addr) {
    asm volatile("ldmatrix.sync.aligned.m8n8.x4.shared.b16 {%0,%1,%2,%3}, [%4];"
                 : "=r"(r0), "=r"(r1), "=r"(r2), "=r"(r3) : "r"(addr));
}

__device__ __forceinline__ uint32_t smem_u32(const void* p) {
    uint32_t a;
    asm("{ .reg .u64 t; cvta.to.shared.u64 t, %1; cvt.u32.u64 %0, t; }"
        : "=r"(a) : "l"(p));
    return a;
}

__device__ __forceinline__ uint32_t h2_bits(__half2 h) {
    return *reinterpret_cast<uint32_t*>(&h);
}

// ---- kernel 0: convert inputs to fp16 in scratch ----
__global__ void __launch_bounds__(256) convert_kernel(
    const float* __restrict__ x,
    const float* __restrict__ Wq, const float* __restrict__ Wk,
    const float* __restrict__ Wv, const float* __restrict__ Wo)
{
    const int z = blockIdx.z;
    const float* src;
    __half* dst;
    size_t n;
    if (z == 0)      { src = x;  dst = g_xh;  n = (size_t)MROWS * EMB; }
    else if (z == 1) { src = Wq; dst = g_wqh; n = (size_t)EMB * EMB; }
    else if (z == 2) { src = Wk; dst = g_wkh; n = (size_t)EMB * EMB; }
    else if (z == 3) { src = Wv; dst = g_wvh; n = (size_t)EMB * EMB; }
    else             { src = Wo; dst = g_woh; n = (size_t)EMB * EMB; }

    const size_t stride = (size_t)gridDim.x * blockDim.x * 4;
    for (size_t i = ((size_t)blockIdx.x * blockDim.x + threadIdx.x) * 4;
         i < n; i += stride) {
        float4 v = *reinterpret_cast<const float4*>(src + i);
        __half2* d2 = reinterpret_cast<__half2*>(dst + i);
        d2[0] = __floats2half2_rn(v.x, v.y);
        d2[1] = __floats2half2_rn(v.z, v.w);
    }
}

// ============================================================================
// 4-stage cp.async fp16 GEMM core, ldmatrix fragment loads.
// C[M,N] = A[M,K] * B[N,K]^T.  BM=BN=128, BK=32 halves, warp tile 64x32.
// smem row = 16 uints (32 halves) + pad 4 -> stride 20 uints (80 B, 16B-aligned;
// 8-row ldmatrix covers banks 4i mod 32 -> conflict-free).
// ============================================================================
#define GH_BM 128
#define GH_BN 128
#define GH_BK 32
#define GH_S  4
#define GH_LDT 20
#define GH_TILE (128 * GH_LDT)               // 2560 uints per operand per stage
#define GH_STG  (2 * GH_TILE)
#define GH_SMEM_BYTES (GH_S * GH_STG * 4)    // 81920 B
#define GH_MT 4
#define GH_NT 4

__device__ __forceinline__ void gemm_core_h(
    const __half* __restrict__ A,
    const __half* __restrict__ B,
    int Kdim, int m0, int n0,
    float (&acc)[GH_MT][GH_NT][4])
{
    extern __shared__ uint32_t smh[];
    const uint32_t sm_b = smem_u32(smh);

    const int tid  = threadIdx.x;
    const int lane = tid & 31;
    const int warp = tid >> 5;
    const int wm = (warp >> 2) * 64;         // 2 warp-rows
    const int wn = (warp & 3) * 32;          // 4 warp-cols
    // ldmatrix lane decomposition
    const int mat  = lane >> 3;              // which 8x8 matrix this lane addresses
    const int rin  = lane & 7;
    const int a_lrow = (mat & 1) * 8 + rin;  // A: row offset within 16-row frag
    const int a_lcol = (mat >> 1) * 4;       // A: uint col offset (0 or 4)
    const int b_sel  = (mat >> 1);           // B: which n-block of the pair
    const int b_lcol = (mat & 1) * 4;        // B: uint col offset

    auto stage = [&](int chunk) {
        const int s = chunk & (GH_S - 1);
        const uint32_t ab = sm_b + (uint32_t)(s * GH_STG) * 4;
        const uint32_t bb = ab + GH_TILE * 4;
        const int k0 = chunk * GH_BK;
        #pragma unroll
        for (int i = 0; i < 2; ++i) {        // 128 rows x 4 cp16 each operand
            int idx = tid + i * 256;
            int row = idx >> 2, q = idx & 3;
            cp16(ab + (uint32_t)(row * GH_LDT + q * 4) * 4,
                 A + (size_t)(m0 + row) * Kdim + k0 + q * 8);
            cp16(bb + (uint32_t)(row * GH_LDT + q * 4) * 4,
                 B + (size_t)(n0 + row) * Kdim + k0 + q * 8);
        }
    };

    const int nchunk = Kdim / GH_BK;
    #pragma unroll
    for (int c = 0; c < GH_S - 1; ++c) {
        stage(c);
        asm volatile("cp.async.commit_group;\n");
    }

    for (int i = 0; i < nchunk; ++i) {
        asm volatile("cp.async.wait_group %0;\n" :: "n"(GH_S - 2));
        __syncthreads();

        const uint32_t ab = sm_b + (uint32_t)((i & (GH_S - 1)) * GH_STG) * 4;
        const uint32_t bb = ab + GH_TILE * 4;
        #pragma unroll
        for (int ks = 0; ks < 2; ++ks) {     // 2 k16 steps per chunk
            uint32_t af[GH_MT][4];
            uint32_t bf[GH_NT][2];
            #pragma unroll
            for (int mt = 0; mt < GH_MT; ++mt) {
                uint32_t ad = ab + (uint32_t)((wm + mt * 16 + a_lrow) * GH_LDT
                                              + ks * 8 + a_lcol) * 4;
                ldsm4(af[mt][0], af[mt][1], af[mt][2], af[mt][3], ad);
            }
            #pragma unroll
            for (int p = 0; p < 2; ++p) {
                uint32_t bd = bb + (uint32_t)((wn + (2 * p + b_sel) * 8 + rin) * GH_LDT
                                              + ks * 8 + b_lcol) * 4;
                ldsm4(bf[2 * p][0], bf[2 * p][1], bf[2 * p + 1][0], bf[2 * p + 1][1], bd);
            }
            #pragma unroll
            for (int mt = 0; mt < GH_MT; ++mt)
                #pragma unroll
                for (int nt = 0; nt < GH_NT; ++nt)
                    mma16(acc[mt][nt], af[mt], bf[nt]);
        }

        if (i + GH_S - 1 < nchunk) stage(i + GH_S - 1);
        asm volatile("cp.async.commit_group;\n");
    }
}

// ---- kernel 1: fused QKV projection (grid.z selects q/k/v) ----
// q,k stored [B,H,S,D]; v stored TRANSPOSED [B,H,D,S] for flash PV mma.
__global__ void __launch_bounds__(256, 2) qkv_kernel(
    const float* __restrict__ bq, const float* __restrict__ bk,
    const float* __restrict__ bv)
{
    const int z = blockIdx.z;
    const __half* W   = (z == 0) ? g_wqh : ((z == 1) ? g_wkh : g_wvh);
    const float* bptr = (z == 0) ? bq    : ((z == 1) ? bk    : bv);
    __half* out       = (z == 0) ? g_qh  : ((z == 1) ? g_kh  : g_vh);

    float acc[GH_MT][GH_NT][4] = {};
    const int m0 = blockIdx.x * GH_BM, n0 = blockIdx.y * GH_BN;
    gemm_core_h(g_xh, W, EMB, m0, n0, acc);

    const int lane = threadIdx.x & 31, warp = threadIdx.x >> 5;
    const int g = lane >> 2, tg = lane & 3;
    const int wm = (warp >> 2) * 64;
    const int wn = (warp & 3) * 32;

    #pragma unroll
    for (int mt = 0; mt < GH_MT; ++mt)
        #pragma unroll
        for (int nt = 0; nt < GH_NT; ++nt) {
            int r = m0 + wm + mt * 16 + g;
            int c = n0 + wn + nt * 8 + 2 * tg;       // even
            float v0 = acc[mt][nt][0] + bptr[c];
            float v1 = acc[mt][nt][1] + bptr[c + 1];
            float v2 = acc[mt][nt][2] + bptr[c];
            float v3 = acc[mt][nt][3] + bptr[c + 1];
            int h = c >> 6, d = c & 63;
            int b0 = r >> 10, s0 = r & 1023;
            int b1 = (r + 8) >> 10, s1 = (r + 8) & 1023;
            if (z < 2) {
                __half2* p0 = reinterpret_cast<__half2*>(
                    out + (((size_t)b0 * NH + h) * SEQ + s0) * HD + d);
                __half2* p1 = reinterpret_cast<__half2*>(
                    out + (((size_t)b1 * NH + h) * SEQ + s1) * HD + d);
                *p0 = __floats2half2_rn(v0, v1);
                *p1 = __floats2half2_rn(v2, v3);
            } else {
                out[(((size_t)b0 * NH + h) * HD + d) * SEQ + s0]     = __float2half_rn(v0);
                out[(((size_t)b0 * NH + h) * HD + d + 1) * SEQ + s0] = __float2half_rn(v1);
                out[(((size_t)b1 * NH + h) * HD + d) * SEQ + s1]     = __float2half_rn(v2);
                out[(((size_t)b1 * NH + h) * HD + d + 1) * SEQ + s1] = __float2half_rn(v3);
            }
        }
}

// ---- kernel 3: out = concat @ Wo^T + bo (fp32 output) ----
__global__ void __launch_bounds__(256, 2) oproj_kernel(
    const float* __restrict__ bo, float* __restrict__ out)
{
    float acc[GH_MT][GH_NT][4] = {};
    const int m0 = blockIdx.x * GH_BM, n0 = blockIdx.y * GH_BN;
    gemm_core_h(g_oh, g_woh, EMB, m0, n0, acc);

    const int lane = threadIdx.x & 31, warp = threadIdx.x >> 5;
    const int g = lane >> 2, tg = lane & 3;
    const int wm = (warp >> 2) * 64;
    const int wn = (warp & 3) * 32;
    #pragma unroll
    for (int mt = 0; mt < GH_MT; ++mt)
        #pragma unroll
        for (int nt = 0; nt < GH_NT; ++nt) {
            int r = m0 + wm + mt * 16 + g;
            int c = n0 + wn + nt * 8 + 2 * tg;
            out[(size_t)r * EMB + c]           = acc[mt][nt][0] + bo[c];
            out[(size_t)r * EMB + c + 1]       = acc[mt][nt][1] + bo[c + 1];
            out[(size_t)(r + 8) * EMB + c]     = acc[mt][nt][2] + bo[c];
            out[(size_t)(r + 8) * EMB + c + 1] = acc[mt][nt][3] + bo[c + 1];
        }
}

// ============================================================================
// kernel 2: fused flash attention, fp16 mma, ldmatrix fragment loads.
// Qu[128][36], Ku[64][36], Vu[64][36] (d-major), Pu[128][36]
// (stride 36 uints = 144 B: 16B-aligned rows, banks 4i mod 32 -> conflict-free)
// ============================================================================
#define FA_BM 128
#define FA_BN 64
#define FA_LDT 36
#define FA_QS (128 * FA_LDT)
#define FA_KS (64 * FA_LDT)
#define FA_VS (64 * FA_LDT)
#define FA_PS (128 * FA_LDT)
#define FA_SMEM_BYTES ((FA_QS + FA_KS + FA_VS + FA_PS + 512) * 4)   // 59392 B

__global__ void __launch_bounds__(256, 2) flash_kernel()
{
    extern __shared__ uint32_t fsh[];
    uint32_t* Qu = fsh;
    uint32_t* Ku = Qu + FA_QS;
    uint32_t* Vu = Ku + FA_KS;
    uint32_t* Pu = Vu + FA_VS;
    float* redA  = (float*)(Pu + FA_PS);     // [2][128]
    float* redB  = redA + 256;               // [2][128]
    const uint32_t qu_b = smem_u32(Qu);
    const uint32_t ku_b = smem_u32(Ku);
    const uint32_t vu_b = smem_u32(Vu);
    const uint32_t pu_b = smem_u32(Pu);

    const int z  = blockIdx.z;
    const int m0 = blockIdx.x * FA_BM;
    const __half* Qh = g_qh + (size_t)z * SEQ * HD;
    const __half* Kh = g_kh + (size_t)z * SEQ * HD;
    const __half* Vh = g_vh + (size_t)z * HD * SEQ;   // [D][S]

    const int tid  = threadIdx.x;
    const int lane = tid & 31, warp = tid >> 5;
    const int g = lane >> 2, tg = lane & 3;
    const int mw = warp >> 1, nw = warp & 1;
    const int wm = mw * 32;
    const int wn = nw * 32;
    // ldmatrix lane decomposition
    const int mat  = lane >> 3, rin = lane & 7;
    const int a_lrow = (mat & 1) * 8 + rin;
    const int a_lcol = (mat >> 1) * 4;
    const int b_sel  = (mat >> 1);
    const int b_lcol = (mat & 1) * 4;

    // stage Q tile once: 128 rows x 8 cp16
    #pragma unroll
    for (int i = 0; i < 4; ++i) {
        int idx = tid + i * 256;
        int r = idx >> 3, q = idx & 7;
        cp16(qu_b + (uint32_t)(r * FA_LDT + q * 4) * 4,
             Qh + (size_t)(m0 + r) * HD + q * 8);
    }
    asm volatile("cp.async.commit_group;\n");

    float acc_o[2][4][4] = {};
    float m_st[2][2] = {{-1e30f, -1e30f}, {-1e30f, -1e30f}};
    float l_st[2][2] = {};

    for (int n0 = 0; n0 < SEQ; n0 += FA_BN) {
        __syncthreads();   // prior iter's Ku/Vu/Pu reads complete

        #pragma unroll
        for (int i = 0; i < 2; ++i) {
            int idx = tid + i * 256;
            int rr = idx >> 3, q = idx & 7;
            cp16(ku_b + (uint32_t)(rr * FA_LDT + q * 4) * 4,
                 Kh + (size_t)(n0 + rr) * HD + q * 8);
            cp16(vu_b + (uint32_t)(rr * FA_LDT + q * 4) * 4,
                 Vh + (size_t)rr * SEQ + n0 + q * 8);
        }
        asm volatile("cp.async.commit_group;\n");
        asm volatile("cp.async.wait_group 0;\n");
        __syncthreads();

        // ---- S = Q K^T (4 k16 steps over D=64) ----
        float acc_s[2][4][4] = {};
        #pragma unroll
        for (int ks = 0; ks < 4; ++ks) {
            uint32_t af[2][4];
            uint32_t bf[4][2];
            #pragma unroll
            for (int mt = 0; mt < 2; ++mt) {
                uint32_t ad = qu_b + (uint32_t)((wm + mt * 16 + a_lrow) * FA_LDT
                                                + ks * 8 + a_lcol) * 4;
                ldsm4(af[mt][0], af[mt][1], af[mt][2], af[mt][3], ad);
            }
            #pragma unroll
            for (int p = 0; p < 2; ++p) {
                uint32_t bd = ku_b + (uint32_t)((wn + (2 * p + b_sel) * 8 + rin) * FA_LDT
                                                + ks * 8 + b_lcol) * 4;
                ldsm4(bf[2 * p][0], bf[2 * p][1], bf[2 * p + 1][0], bf[2 * p + 1][1], bd);
            }
            #pragma unroll
            for (int mt = 0; mt < 2; ++mt)
                #pragma unroll
                for (int nt = 0; nt < 4; ++nt)
                    mma16(acc_s[mt][nt], af[mt], bf[nt]);
        }
        #pragma unroll
        for (int mt = 0; mt < 2; ++mt)
            #pragma unroll
            for (int nt = 0; nt < 4; ++nt)
                #pragma unroll
                for (int e = 0; e < 4; ++e)
                    acc_s[mt][nt][e] *= 0.125f;

        // ---- row max (quad shuffle + cross-nw smem) ----
        #pragma unroll
        for (int mt = 0; mt < 2; ++mt)
            #pragma unroll
            for (int h = 0; h < 2; ++h) {
                float m = -1e30f;
                #pragma unroll
                for (int nt = 0; nt < 4; ++nt)
                    m = fmaxf(m, fmaxf(acc_s[mt][nt][2 * h], acc_s[mt][nt][2 * h + 1]));
                m = fmaxf(m, __shfl_xor_sync(0xffffffffu, m, 1));
                m = fmaxf(m, __shfl_xor_sync(0xffffffffu, m, 2));
                if (tg == 0) redA[nw * 128 + wm + mt * 16 + g + 8 * h] = m;
            }
        __syncthreads();

        // ---- online softmax + write P (half2 packed) ----
        #pragma unroll
        for (int mt = 0; mt < 2; ++mt)
            #pragma unroll
            for (int h = 0; h < 2; ++h) {
                int row = wm + mt * 16 + g + 8 * h;
                float m = fmaxf(redA[row], redA[128 + row]);
                float mnew = fmaxf(m_st[mt][h], m);
                float scale = __expf(m_st[mt][h] - mnew);
                m_st[mt][h] = mnew;
                l_st[mt][h] *= scale;
                #pragma unroll
                for (int nt = 0; nt < 4; ++nt) {
                    acc_o[mt][nt][2 * h]     *= scale;
                    acc_o[mt][nt][2 * h + 1] *= scale;
                }
                float rs = 0.f;
                #pragma unroll
                for (int nt = 0; nt < 4; ++nt) {
                    float p0 = __expf(acc_s[mt][nt][2 * h]     - mnew);
                    float p1 = __expf(acc_s[mt][nt][2 * h + 1] - mnew);
                    rs += p0 + p1;
                    Pu[row * FA_LDT + (wn >> 1) + nt * 4 + tg] =
                        h2_bits(__floats2half2_rn(p0, p1));
                }
                rs += __shfl_xor_sync(0xffffffffu, rs, 1);
                rs += __shfl_xor_sync(0xffffffffu, rs, 2);
                if (tg == 0) redB[nw * 128 + row] = rs;
            }
        __syncthreads();   // P + redB visible across warps

        #pragma unroll
        for (int mt = 0; mt < 2; ++mt)
            #pragma unroll
            for (int h = 0; h < 2; ++h) {
                int row = wm + mt * 16 + g + 8 * h;
                l_st[mt][h] += redB[row] + redB[128 + row];
            }

        // ---- O += P V (4 k16 steps over 64 keys) ----
        #pragma unroll
        for (int ks = 0; ks < 4; ++ks) {
            uint32_t af[2][4];
            uint32_t bf[4][2];
            #pragma unroll
            for (int mt = 0; mt < 2; ++mt) {
                uint32_t ad = pu_b + (uint32_t)((wm + mt * 16 + a_lrow) * FA_LDT
                                                + ks * 8 + a_lcol) * 4;
                ldsm4(af[mt][0], af[mt][1], af[mt][2], af[mt][3], ad);
            }
            #pragma unroll
            for (int p = 0; p < 2; ++p) {
                uint32_t bd = vu_b + (uint32_t)((wn + (2 * p + b_sel) * 8 + rin) * FA_LDT
                                                + ks * 8 + b_lcol) * 4;
                ldsm4(bf[2 * p][0], bf[2 * p][1], bf[2 * p + 1][0], bf[2 * p + 1][1], bd);
            }
            #pragma unroll
            for (int mt = 0; mt < 2; ++mt)
                #pragma unroll
                for (int nt = 0; nt < 4; ++nt)
                    mma16(acc_o[mt][nt], af[mt], bf[nt]);
        }
    }

    // ---- epilogue: O /= l, half2 stores into concat layout [B,S,H*D] ----
    const int b = z >> 4, h = z & 15;
    #pragma unroll
    for (int mt = 0; mt < 2; ++mt) {
        float inv0 = 1.0f / l_st[mt][0];
        float inv1 = 1.0f / l_st[mt][1];
        #pragma unroll
        for (int nt = 0; nt < 4; ++nt) {
            int s0 = m0 + wm + mt * 16 + g;
            int d0 = wn + nt * 8 + 2 * tg;           // even
            size_t base0 = ((size_t)(b * SEQ + s0)) * EMB + h * HD + d0;
            size_t base1 = ((size_t)(b * SEQ + s0 + 8)) * EMB + h * HD + d0;
            *reinterpret_cast<__half2*>(g_oh + base0) =
                __floats2half2_rn(acc_o[mt][nt][0] * inv0, acc_o[mt][nt][1] * inv0);
            *reinterpret_cast<__half2*>(g_oh + base1) =
                __floats2half2_rn(acc_o[mt][nt][2] * inv1, acc_o[mt][nt][3] * inv1);
        }
    }
}

extern "C" void kernel_launch(void* const* d_in, const int* in_sizes, int n_in,
                              void* d_out, int out_size)
{
    const float* x  = (const float*)d_in[0];
    const float* Wq = (const float*)d_in[1];
    const float* bq = (const float*)d_in[2];
    const float* Wk = (const float*)d_in[3];
    const float* bk = (const float*)d_in[4];
    const float* Wv = (const float*)d_in[5];
    const float* bv = (const float*)d_in[6];
    const float* Wo = (const float*)d_in[7];
    const float* bo = (const float*)d_in[8];
    float* out = (float*)d_out;

    cudaFuncSetAttribute(qkv_kernel,
                         cudaFuncAttributeMaxDynamicSharedMemorySize, GH_SMEM_BYTES);
    cudaFuncSetAttribute(oproj_kernel,
                         cudaFuncAttributeMaxDynamicSharedMemorySize, GH_SMEM_BYTES);
    cudaFuncSetAttribute(flash_kernel,
                         cudaFuncAttributeMaxDynamicSharedMemorySize, FA_SMEM_BYTES);

    convert_kernel<<<dim3(1024, 1, 5), 256>>>(x, Wq, Wk, Wv, Wo);
    qkv_kernel<<<dim3(MROWS / GH_BM, EMB / GH_BN, 3), 256, GH_SMEM_BYTES>>>(bq, bk, bv);
    flash_kernel<<<dim3(SEQ / FA_BM, 1, BH), 256, FA_SMEM_BYTES>>>();
    oproj_kernel<<<dim3(MROWS / GH_BM, EMB / GH_BN, 1), 256, GH_SMEM_BYTES>>>(bo, out);
}